// round 17
// baseline (speedup 1.0000x reference)
#include <cuda_runtime.h>

// SinkhornScorer fused kernel for GB300 (sm_103a).
// R17: 2 warps per batch, COLUMN-split (warp h owns cols h*32..h*32+31, all
// 64 rows). Thread tile 8 rows x 8 cols -> kreg 32 u64 (converted in place
// from acc) -> ~125 regs -> 2 CTAs/SM (16 warps). Sinkhorn: v-phase
// warp-local; u-phase via 65-float double-buffered smem exchange + named
// barrier per pair (1/iter). GEMM: per-lane 1 x row + 1 y row staging
// (stats reduction-free), double-buffered, 1 named barrier per chunk.

namespace {
constexpr int NP = 65;
constexpr float LOG128 = 4.852030263919617f;
constexpr float MU_IN  = 0.0078125f;   // 1/128
constexpr float MU_DB  = 0.5f;         // 64/128

__device__ __forceinline__ float warp_sum(float v) {
#pragma unroll
    for (int o = 16; o; o >>= 1) v += __shfl_xor_sync(0xffffffffu, v, o);
    return v;
}
__device__ __forceinline__ unsigned long long ffma2(
    unsigned long long a, unsigned long long b, unsigned long long c) {
    unsigned long long d;
    asm("fma.rn.f32x2 %0, %1, %2, %3;" : "=l"(d) : "l"(a), "l"(b), "l"(c));
    return d;
}
__device__ __forceinline__ unsigned long long fmul2(
    unsigned long long a, unsigned long long b) {
    unsigned long long d;
    asm("mul.rn.f32x2 %0, %1, %2;" : "=l"(d) : "l"(a), "l"(b));
    return d;
}
__device__ __forceinline__ unsigned long long fadd2(
    unsigned long long a, unsigned long long b) {
    unsigned long long d;
    asm("add.rn.f32x2 %0, %1, %2;" : "=l"(d) : "l"(a), "l"(b));
    return d;
}
__device__ __forceinline__ unsigned long long pack2(float lo, float hi) {
    unsigned long long d;
    asm("mov.b64 %0, {%1, %2};" : "=l"(d) : "f"(lo), "f"(hi));
    return d;
}
__device__ __forceinline__ void unpack2(unsigned long long v, float& lo, float& hi) {
    asm("mov.b64 {%0, %1}, %2;" : "=f"(lo), "=f"(hi) : "l"(v));
}
__device__ __forceinline__ float pairsum(unsigned long long v) {
    float lo, hi; unpack2(v, lo, hi); return lo + hi;
}
}  // namespace

#define BARP(id) asm volatile("bar.sync %0, 64;" :: "r"(id) : "memory")

__global__ void __launch_bounds__(256, 2) sinkhorn_fused_kernel(
    const float* __restrict__ x, const float* __restrict__ y,
    const float* __restrict__ gamma, const float* __restrict__ beta,
    const float* __restrict__ wdb, const float* __restrict__ bdb,
    float* __restrict__ out_match, float* __restrict__ out_score,
    int write_score)
{
    const int t     = threadIdx.x;
    const int lane  = t & 31;
    const int w     = t >> 5;
    const int h     = w & 1;        // pair member: column half
    const int pair  = w >> 1;       // 0..3 -> batch within CTA
    const int barid = 1 + pair;
    const int batch = blockIdx.x * 4 + pair;
    const int rg    = lane >> 2;    // rows rg*8 .. rg*8+7
    const int cg    = lane & 3;
    const int cbase = h * 32 + cg * 8;   // own 8 columns
    const int rstg  = h * 32 + lane;     // staged x/y row

    __shared__ float sGw[256];
    __shared__ float sRed[16];
    __shared__ float sCst[2];
    __shared__ __align__(16) float4 sX[4][2][64];   // per-batch x, swizzled
    __shared__ __align__(16) float  sY[4][2][256];  // per-batch y, k-major
    __shared__ float sSA[4][256];   // [0:64) xscale [64:128) yscale
                                    // [128:192) xalpha [192:256) yalpha
    __shared__ float sEx[4][2][2][68];  // [pair][parity][h][row partials+zz]
    __shared__ float sP[8];

    // ---- prologue constants ----
    {
        float gwv = gamma[t] * wdb[t];
        float bwv = beta[t] * wdb[t];
        sGw[t] = gwv;
        gwv = warp_sum(gwv);
        bwv = warp_sum(bwv);
        if (lane == 0) { sRed[w] = gwv; sRed[8 + w] = bwv; }
    }
    __syncthreads();
    if (t == 0) {
        float a = 0.f, c = 0.f;
#pragma unroll
        for (int i = 0; i < 8; i++) { a += sRed[i]; c += sRed[8 + i]; }
        sCst[0] = a;
        sCst[1] = c + bdb[0];
    }
    __syncthreads();
    const float Sgw = sCst[0], Sbw = sCst[1];

    const float4* xg4 = (const float4*)(x + (size_t)batch * 64 * 256);
    const float4* yg4 = (const float4*)(y + (size_t)batch * 64 * 256);
    const float4* gw4 = (const float4*)sGw;

    // ---- GEMM: kr[r][cp] = acc for (row rg*8+r) x cols (cbase+2cp, +1) ----
    unsigned long long kr[8][4];
#pragma unroll
    for (int r = 0; r < 8; r++)
#pragma unroll
        for (int cp = 0; cp < 4; cp++) kr[r][cp] = 0ull;

    float s1x = 0.f, s2x = 0.f, s3x = 0.f;
    float s1y = 0.f, s2y = 0.f, s3y = 0.f;
    const int xslot = rstg ^ (rstg >> 3);

    float4 px = xg4[rstg * 64], py = yg4[rstg * 64];

#pragma unroll 1
    for (int kc = 0; kc < 64; kc++) {
        float4* Xb = sX[pair][kc & 1];
        float*  Yb = sY[pair][kc & 1];
        Xb[xslot] = px;
        Yb[0 * 64 + rstg] = py.x;
        Yb[1 * 64 + rstg] = py.y;
        Yb[2 * 64 + rstg] = py.z;
        Yb[3 * 64 + rstg] = py.w;
        {   // fused per-row stats (lane owns exactly one x row, one y row)
            float4 gq = gw4[kc];
            s1x += (px.x + px.y) + (px.z + px.w);
            s2x += px.x * px.x + px.y * px.y + px.z * px.z + px.w * px.w;
            s3x += px.x * gq.x + px.y * gq.y + px.z * gq.z + px.w * gq.w;
            s1y += (py.x + py.y) + (py.z + py.w);
            s2y += py.x * py.x + py.y * py.y + py.z * py.z + py.w * py.w;
            s3y += py.x * gq.x + py.y * gq.y + py.z * gq.z + py.w * gq.w;
        }
        BARP(barid);
        if (kc < 63) {
            px = xg4[rstg * 64 + kc + 1];
            py = yg4[rstg * 64 + kc + 1];
        }
        const float* Xs = (const float*)Xb;
#pragma unroll
        for (int k = 0; k < 4; k++) {
            ulonglong2 ya  = *(const ulonglong2*)(Yb + k * 64 + cbase);
            ulonglong2 yb2 = *(const ulonglong2*)(Yb + k * 64 + cbase + 4);
#pragma unroll
            for (int r = 0; r < 8; r++) {
                int row = rg * 8 + r;
                float xs = Xs[((row ^ (row >> 3)) << 2) + k];
                unsigned long long xx = pack2(xs, xs);
                kr[r][0] = ffma2(xx, ya.x,  kr[r][0]);
                kr[r][1] = ffma2(xx, ya.y,  kr[r][1]);
                kr[r][2] = ffma2(xx, yb2.x, kr[r][2]);
                kr[r][3] = ffma2(xx, yb2.y, kr[r][3]);
            }
        }
    }

    // ---- stats finalize (no reduction needed) ----
    {
        float* SA = sSA[pair];
        SA[rstg] = 1.0f / fmaxf(sqrtf(s2x), 1e-12f);
        float mu  = s1x * (1.0f / 256.0f);
        float var = s2x * (1.0f / 256.0f) - mu * mu;
        SA[128 + rstg] = tanhf(rsqrtf(var + 1e-5f) * (s3x - mu * Sgw) + Sbw);
        SA[64 + rstg] = 1.0f / fmaxf(sqrtf(s2y), 1e-12f);
        float muy  = s1y * (1.0f / 256.0f);
        float vary = s2y * (1.0f / 256.0f) - muy * muy;
        SA[192 + rstg] = tanhf(rsqrtf(vary + 1e-5f) * (s3y - muy * Sgw) + Sbw);
    }
    BARP(barid);   // both warps' stats visible (x scales span both halves)

    // ---- convert acc -> K = exp(10 * cos) IN PLACE ----
    float kcol64[8];
    unsigned long long kdrow[4];
    {
        const float* SA = sSA[pair];
        float sj[8];
#pragma unroll
        for (int c = 0; c < 8; c++) sj[c] = SA[64 + cbase + c] * 10.0f;
#pragma unroll
        for (int r = 0; r < 8; r++) {
            float si = SA[rg * 8 + r];
#pragma unroll
            for (int cp = 0; cp < 4; cp++) {
                float c0, c1;
                unpack2(kr[r][cp], c0, c1);
                kr[r][cp] = pack2(__expf(c0 * si * sj[2 * cp]),
                                  __expf(c1 * si * sj[2 * cp + 1]));
            }
            kcol64[r] = __expf(10.0f * SA[128 + rg * 8 + r]);
        }
#pragma unroll
        for (int cp = 0; cp < 4; cp++)
            kdrow[cp] = pack2(__expf(10.0f * SA[192 + cbase + 2 * cp]),
                              __expf(10.0f * SA[192 + cbase + 2 * cp + 1]));
    }

    // ---- Sinkhorn: 20 iterations, 1 named barrier each ----
    unsigned long long b2[4];
#pragma unroll
    for (int cp = 0; cp < 4; cp++) b2[cp] = pack2(1.f, 1.f);
    float b64 = 1.f, a64 = 0.f;
    float a[8];

#pragma unroll 1
    for (int it = 0; it < 20; it++) {
        // u-phase partials over own 32 cols (reduce cg: xor 1, 2)
        float z[8];
#pragma unroll
        for (int r = 0; r < 8; r++) {
            unsigned long long s = fmul2(kr[r][0], b2[0]);
            s = ffma2(kr[r][1], b2[1], s);
            s = ffma2(kr[r][2], b2[2], s);
            s = ffma2(kr[r][3], b2[3], s);
            z[r] = pairsum(s);
        }
#pragma unroll
        for (int r = 0; r < 8; r++) {
            z[r] += __shfl_xor_sync(0xffffffffu, z[r], 1);
            z[r] += __shfl_xor_sync(0xffffffffu, z[r], 2);
        }
        float zz;   // dustbin-row partial over own cols
        {
            unsigned long long s = fmul2(kdrow[0], b2[0]);
            s = ffma2(kdrow[1], b2[1], s);
            s = ffma2(kdrow[2], b2[2], s);
            s = ffma2(kdrow[3], b2[3], s);
            zz = pairsum(s);
            zz += __shfl_xor_sync(0xffffffffu, zz, 1);
            zz += __shfl_xor_sync(0xffffffffu, zz, 2);
        }
        // exchange partials with partner warp (double-buffered)
        {
            float* P = &sEx[pair][it & 1][h][0];
            if (cg == 0) {
#pragma unroll
                for (int r = 0; r < 8; r++) P[rg * 8 + r] = z[r];
                if (lane == 0) P[64] = zz;
            }
        }
        BARP(barid);
        const float* Q = &sEx[pair][it & 1][h ^ 1][0];
        a64 = __fdividef(MU_DB, zz + Q[64]);
#pragma unroll
        for (int r = 0; r < 8; r++)
            a[r] = __fdividef(MU_IN,
                              fmaf(kcol64[r], b64, z[r] + Q[rg * 8 + r]));

        // v-phase: col sums over all 64 rows (warp-local; cols are ours)
        unsigned long long q[4];
        {
            unsigned long long a642 = pack2(a64, a64);
#pragma unroll
            for (int cp = 0; cp < 4; cp++)
                q[cp] = (rg == 0) ? fmul2(kdrow[cp], a642) : 0ull;
        }
        float zb = 0.f;
#pragma unroll
        for (int r = 0; r < 8; r++) {
            unsigned long long ar2 = pack2(a[r], a[r]);
#pragma unroll
            for (int cp = 0; cp < 4; cp++) q[cp] = ffma2(kr[r][cp], ar2, q[cp]);
            zb = fmaf(kcol64[r], a[r], zb);
        }
#pragma unroll
        for (int off = 4; off <= 16; off <<= 1) {
#pragma unroll
            for (int cp = 0; cp < 4; cp++)
                q[cp] = fadd2(q[cp], __shfl_xor_sync(0xffffffffu, q[cp], off));
            zb += __shfl_xor_sync(0xffffffffu, zb, off);
        }
#pragma unroll
        for (int cp = 0; cp < 4; cp++) {
            float q0, q1;
            unpack2(q[cp], q0, q1);
            b2[cp] = pack2(__fdividef(MU_IN, q0), __fdividef(MU_IN, q1));
        }
        b64 = __fdividef(MU_DB, zb);
    }

    // ---- epilogue: matching (C = __logf(K)) + score ----
    float lb[8];
#pragma unroll
    for (int cp = 0; cp < 4; cp++) {
        float q0, q1;
        unpack2(b2[cp], q0, q1);
        lb[2 * cp]     = __logf(q0);
        lb[2 * cp + 1] = __logf(q1);
    }
    const float la64l = __logf(a64);
    const float lb64l = __logf(b64);
    float* om = out_match + (size_t)batch * (NP * NP);
    const float* SA = sSA[pair];
    float p = 0.f;
#pragma unroll
    for (int r = 0; r < 8; r++) {
        int row = rg * 8 + r;
        float laf = __logf(a[r]) + LOG128;
        float* orow = om + row * NP + cbase;
#pragma unroll
        for (int cp = 0; cp < 4; cp++) {
            float k0, k1, bb0, bb1;
            unpack2(kr[r][cp], k0, k1);
            unpack2(b2[cp], bb0, bb1);
            float c0 = __logf(k0);
            float c1 = __logf(k1);
            orow[2 * cp]     = c0 + laf + lb[2 * cp];
            orow[2 * cp + 1] = c1 + laf + lb[2 * cp + 1];
            p += a[r] * (k0 * c0 * bb0 + k1 * c1 * bb1);
        }
        if (h == 0 && cg == 0)
            om[row * NP + 64] = 10.0f * SA[128 + row] + laf + lb64l;
    }
    if (rg == 0) {
#pragma unroll
        for (int c = 0; c < 8; c++) {
            int col = cbase + c;
            om[64 * NP + col] = 10.0f * SA[192 + col] + la64l + LOG128 + lb[c];
        }
    }
    if (h == 0 && lane == 0)
        om[64 * NP + 64] = -1000.0f + la64l + lb64l + LOG128;

    if (write_score) p = warp_sum(p);
    if (lane == 0) sP[w] = p;
    __syncthreads();
    if (write_score && t < 4)
        out_score[blockIdx.x * 4 + t] = (sP[2 * t] + sP[2 * t + 1]) * 128.0f;
}

extern "C" void kernel_launch(void* const* d_in, const int* in_sizes, int n_in,
                              void* d_out, int out_size) {
    const float* x     = (const float*)d_in[0];
    const float* y     = (const float*)d_in[1];
    const float* gamma = (const float*)d_in[2];
    const float* beta  = (const float*)d_in[3];
    const float* wdb   = (const float*)d_in[4];
    const float* bdb   = (const float*)d_in[5];

    int B = in_sizes[0] / (64 * 256);               // 4096 (multiple of 4)
    size_t msz = (size_t)B * NP * NP;
    float* out_match = (float*)d_out;
    float* out_score = (float*)d_out + msz;
    int write_score = ((size_t)out_size >= msz + (size_t)B) ? 1 : 0;

    sinkhorn_fused_kernel<<<B / 4, 256>>>(x, y, gamma, beta, wdb, bdb,
                                          out_match, out_score, write_score);
}